// round 2
// baseline (speedup 1.0000x reference)
#include <cuda_runtime.h>

// Problem constants (B=4, S=2048, H=1024, E=8, K=2)
#define NTOK  8192
#define HDIM  1024
#define NEXP  8

// Static device scratch (allocation-free per harness rules).
__device__ int   g_is64;                          // 1 if top_k_index is int64, 0 if int32
__device__ int   g_nzodd;                         // scratch for dtype detection
__device__ int   g_cnt[NEXP];
__device__ int   g_list[NEXP][NTOK];
__device__ float g_h1[(size_t)2 * NTOK * HDIM];   // 64 MB: relu(x@w1+b1), slot-indexed
__device__ float g_y2[(size_t)2 * NTOK * HDIM];   // 64 MB: h1@w2+b2,      slot-indexed

__global__ void zero_cnt_kernel() {
    if (threadIdx.x < NEXP) g_cnt[threadIdx.x] = 0;
    if (threadIdx.x == 0)   g_nzodd = 0;
}

// Detect index dtype. The buffer has 2*NTOK elements. If int64, words
// 1,3,5,... of the first 16384 words are high halves of small values -> all 0.
// If int32, they are 8192 random expert ids in [0,8) -> some nonzero.
// Scanning only the first 16384 words is in-bounds for both layouts.
__global__ void detect_kernel(const int* __restrict__ idx_words) {
    int acc = 0;
    for (int i = 2 * (blockIdx.x * blockDim.x + threadIdx.x) + 1;
         i < 2 * NTOK; i += 2 * gridDim.x * blockDim.x)
        acc |= idx_words[i];
    if (acc) atomicOr(&g_nzodd, 1);
}

__global__ void set_flag_kernel() {
    if (threadIdx.x == 0) g_is64 = (g_nzodd == 0) ? 1 : 0;
}

__device__ __forceinline__ int load_idx(const void* idx, int pos, int is64) {
    return is64 ? (int)((const long long*)idx)[pos] : ((const int*)idx)[pos];
}

// Build per-expert slot lists. slot = 2*t + k. Duplicate expert within a
// token's top-2 is deduped here (weight merge happens in combine).
__global__ void route_kernel(const void* __restrict__ idx) {
    int t = blockIdx.x * blockDim.x + threadIdx.x;
    if (t >= NTOK) return;
    int is64 = g_is64;
    int e0 = load_idx(idx, 2 * t, is64) & 7;
    int e1 = load_idx(idx, 2 * t + 1, is64) & 7;
    int p0 = atomicAdd(&g_cnt[e0], 1);
    g_list[e0][p0] = 2 * t;
    if (e1 != e0) {
        int p1 = atomicAdd(&g_cnt[e1], 1);
        g_list[e1][p1] = 2 * t + 1;
    }
}

// Gathered-row fp32 SGEMM, 128x128 tile, BK=16, 256 threads, 8x8/thread.
// phase 1: A = hidden[slot>>1], Out = g_h1, relu.   phase 2: A = g_h1[slot], Out = g_y2.
__global__ void __launch_bounds__(256, 2)
expert_gemm_kernel(const float* __restrict__ X,
                   const float* __restrict__ W,
                   const float* __restrict__ Bias,
                   int phase)
{
    __shared__ float As[16][128];   // K-major
    __shared__ float Bs[16][128];
    __shared__ int   s_slot[128];

    const int e   = blockIdx.z;
    const int cnt = g_cnt[e];
    const int m0  = blockIdx.y * 128;
    if (m0 >= cnt) return;
    const int n0  = blockIdx.x * 128;
    const int tid = threadIdx.x;

    const float* Asrc  = (phase == 1) ? X : g_h1;
    float*       Out   = (phase == 1) ? g_h1 : g_y2;
    const int    shift = (phase == 1) ? 1 : 0;   // slot -> A row

    if (tid < 128) {
        int mi = m0 + tid;
        s_slot[tid] = (mi < cnt) ? g_list[e][mi] : -1;
    }
    __syncthreads();

    // A-load mapping: lane-contiguous rows for conflict-free smem stores
    const int ai = tid & 127;
    const int ah = tid >> 7;              // which K-half (0..7 / 8..15)
    const int aslot  = s_slot[ai];
    const bool avalid = (aslot >= 0);
    const float* arow = avalid ? (Asrc + (size_t)(aslot >> shift) * HDIM) : X;

    // B-load mapping: warp = K-row, lanes cover 128 floats coalesced
    const int bw = tid >> 5;
    const int bl = tid & 31;
    const float* wbase = W + (size_t)e * HDIM * HDIM + n0;

    const int tx = tid & 15;
    const int ty = tid >> 4;

    float acc[8][8];
    #pragma unroll
    for (int i = 0; i < 8; i++)
        #pragma unroll
        for (int j = 0; j < 8; j++) acc[i][j] = 0.f;

    for (int kk = 0; kk < HDIM; kk += 16) {
        #pragma unroll
        for (int rep = 0; rep < 2; rep++) {
            int c0 = ah * 8 + rep * 4;
            float4 v = make_float4(0.f, 0.f, 0.f, 0.f);
            if (avalid) v = *(const float4*)(arow + kk + c0);
            As[c0 + 0][ai] = v.x;
            As[c0 + 1][ai] = v.y;
            As[c0 + 2][ai] = v.z;
            As[c0 + 3][ai] = v.w;
        }
        #pragma unroll
        for (int rep = 0; rep < 2; rep++) {
            int c = rep * 8 + bw;
            float4 v = *(const float4*)(wbase + (size_t)(kk + c) * HDIM + bl * 4);
            *(float4*)&Bs[c][bl * 4] = v;
        }
        __syncthreads();

        #pragma unroll
        for (int k = 0; k < 16; k++) {
            float a[8], b[8];
            *(float4*)&a[0] = *(const float4*)&As[k][ty * 8];
            *(float4*)&a[4] = *(const float4*)&As[k][ty * 8 + 4];
            *(float4*)&b[0] = *(const float4*)&Bs[k][tx * 8];
            *(float4*)&b[4] = *(const float4*)&Bs[k][tx * 8 + 4];
            #pragma unroll
            for (int i = 0; i < 8; i++)
                #pragma unroll
                for (int j = 0; j < 8; j++)
                    acc[i][j] += a[i] * b[j];
        }
        __syncthreads();
    }

    // Epilogue: +bias, optional relu, scatter to slot-indexed scratch.
    float bias[8];
    *(float4*)&bias[0] = *(const float4*)(Bias + (size_t)e * HDIM + n0 + tx * 8);
    *(float4*)&bias[4] = *(const float4*)(Bias + (size_t)e * HDIM + n0 + tx * 8 + 4);

    const bool do_relu = (phase == 1);
    #pragma unroll
    for (int i = 0; i < 8; i++) {
        int mi = m0 + ty * 8 + i;
        if (mi < cnt) {
            int slot = s_slot[ty * 8 + i];
            float* o = Out + (size_t)slot * HDIM + n0 + tx * 8;
            float v[8];
            #pragma unroll
            for (int j = 0; j < 8; j++) {
                float x = acc[i][j] + bias[j];
                v[j] = do_relu ? fmaxf(x, 0.f) : x;
            }
            *(float4*)&o[0] = *(const float4*)&v[0];
            *(float4*)&o[4] = *(const float4*)&v[4];
        }
    }
}

// out[t] = (w0 + [e1==e0]*w1) * y2[2t] + [e1!=e0] * w1 * y2[2t+1]
__global__ void combine_kernel(const void* __restrict__ idx,
                               const float* __restrict__ wts,
                               float* __restrict__ out)
{
    int g = blockIdx.x * blockDim.x + threadIdx.x;
    if (g >= NTOK * (HDIM / 4)) return;
    int t = g / (HDIM / 4);
    int f = (g % (HDIM / 4)) * 4;
    int is64 = g_is64;
    int e0 = load_idx(idx, 2 * t, is64) & 7;
    int e1 = load_idx(idx, 2 * t + 1, is64) & 7;
    float w0  = wts[2 * t];
    float w1v = wts[2 * t + 1];
    float w0e = w0 + ((e1 == e0) ? w1v : 0.f);

    float4 a = *(const float4*)(g_y2 + (size_t)(2 * t) * HDIM + f);
    float4 r;
    r.x = w0e * a.x; r.y = w0e * a.y; r.z = w0e * a.z; r.w = w0e * a.w;
    if (e1 != e0) {
        float4 b = *(const float4*)(g_y2 + (size_t)(2 * t + 1) * HDIM + f);
        r.x += w1v * b.x; r.y += w1v * b.y; r.z += w1v * b.z; r.w += w1v * b.w;
    }
    *(float4*)(out + (size_t)t * HDIM + f) = r;
}

extern "C" void kernel_launch(void* const* d_in, const int* in_sizes, int n_in,
                              void* d_out, int out_size)
{
    const float* hidden = (const float*)d_in[0];
    const void*  idx    = d_in[1];                 // int32 or int64, detected on device
    const float* wts    = (const float*)d_in[2];
    const float* w1     = (const float*)d_in[3];
    const float* b1     = (const float*)d_in[4];
    const float* w2     = (const float*)d_in[5];
    const float* b2     = (const float*)d_in[6];
    float*       out    = (float*)d_out;

    zero_cnt_kernel<<<1, 32>>>();
    detect_kernel<<<16, 256>>>((const int*)idx);
    set_flag_kernel<<<1, 32>>>();
    route_kernel<<<(NTOK + 255) / 256, 256>>>(idx);

    // grid: (N-tiles, worst-case M-tiles, experts); oversubscribed tiles exit early.
    dim3 grid(HDIM / 128, NTOK / 128, NEXP);
    expert_gemm_kernel<<<grid, 256>>>(hidden, w1, b1, 1);
    expert_gemm_kernel<<<grid, 256>>>(hidden, w2, b2, 2);

    combine_kernel<<<(NTOK * (HDIM / 4) + 255) / 256, 256>>>(idx, wts, out);
}

// round 8
// speedup vs baseline: 2.3800x; 2.3800x over previous
#include <cuda_runtime.h>
#include <cuda_bf16.h>
#include <cstdint>

// Problem constants (B=4, S=2048, H=1024, E=8, K=2)
#define NTOK  8192
#define HDIM  1024
#define NEXP  8

// ---------------------------------------------------------------------------
// Single aliased scratch arena: 134,217,728 B total (matches the R2-proven
// static footprint). Regions by phase:
//   [0,   32M):  phase1 = x-split (hi@0, lo@16M) | phase2 = w2-split (hi@0, lo@16M)
//   [32M, 64M):  phase1 = w1-split (hi,lo)       | phase2 = scratch2 fp32 [NTOK][HDIM]
//   [64M,128M):  h1-split (hi@64M, lo@96M), live both phases
// ---------------------------------------------------------------------------
#define A_XHI   ((size_t)0)
#define A_XLO   ((size_t)16777216)
#define A_W2HI  ((size_t)0)
#define A_W2LO  ((size_t)16777216)
#define A_W1HI  ((size_t)33554432)
#define A_W1LO  ((size_t)50331648)
#define A_SCR2  ((size_t)33554432)
#define A_H1HI  ((size_t)67108864)
#define A_H1LO  ((size_t)100663296)

__device__ __align__(256) unsigned char g_arena[134217728];
__device__ int g_is64, g_nzodd;
__device__ int g_cnt[NEXP];
__device__ int g_list[NEXP][NTOK];

// ---------------------------------------------------------------------------
// PTX helpers — all plain compute_100 (mma.sync / ldmatrix / cp.async)
// ---------------------------------------------------------------------------
__device__ __forceinline__ uint32_t smem_u32(const void* p) {
    uint32_t a;
    asm("{ .reg .u64 t; cvta.to.shared.u64 t, %1; cvt.u32.u64 %0, t; }" : "=r"(a) : "l"(p));
    return a;
}
__device__ __forceinline__ void cp16(uint32_t dst, const void* src, uint32_t nbytes) {
    asm volatile("cp.async.cg.shared.global [%0], [%1], 16, %2;"
                 :: "r"(dst), "l"(src), "r"(nbytes) : "memory");
}
#define CP_COMMIT() asm volatile("cp.async.commit_group;" ::: "memory")
#define CP_WAIT(n)  asm volatile("cp.async.wait_group %0;" :: "n"(n) : "memory")

#define LDM_X4(r, a)                                                        \
    asm volatile("ldmatrix.sync.aligned.m8n8.x4.shared.b16 {%0,%1,%2,%3}, [%4];" \
        : "=r"((r)[0]), "=r"((r)[1]), "=r"((r)[2]), "=r"((r)[3]) : "r"(a))
#define LDM_X2T(r, a)                                                       \
    asm volatile("ldmatrix.sync.aligned.m8n8.x2.trans.shared.b16 {%0,%1}, [%2];" \
        : "=r"((r)[0]), "=r"((r)[1]) : "r"(a))

#define MMA_BF16(c, A, B)                                                   \
    asm volatile("mma.sync.aligned.m16n8k16.row.col.f32.bf16.bf16.f32 "     \
        "{%0,%1,%2,%3}, {%4,%5,%6,%7}, {%8,%9}, {%0,%1,%2,%3};"             \
        : "+f"((c)[0]), "+f"((c)[1]), "+f"((c)[2]), "+f"((c)[3])            \
        : "r"((A)[0]), "r"((A)[1]), "r"((A)[2]), "r"((A)[3]),               \
          "r"((B)[0]), "r"((B)[1]))

// ---------------------------------------------------------------------------
// Routing / dtype detection
// ---------------------------------------------------------------------------
__global__ void zero_cnt_kernel() {
    if (threadIdx.x < NEXP) g_cnt[threadIdx.x] = 0;
    if (threadIdx.x == 0)   g_nzodd = 0;
}
__global__ void detect_kernel(const int* __restrict__ w) {
    int acc = 0;
    for (int i = 2 * (blockIdx.x * blockDim.x + threadIdx.x) + 1;
         i < 2 * NTOK; i += 2 * gridDim.x * blockDim.x) acc |= w[i];
    if (acc) atomicOr(&g_nzodd, 1);
}
__global__ void set_flag_kernel() { if (threadIdx.x == 0) g_is64 = (g_nzodd == 0); }

__device__ __forceinline__ int load_idx(const void* idx, int pos, int is64) {
    return is64 ? (int)((const long long*)idx)[pos] : ((const int*)idx)[pos];
}
__global__ void route_kernel(const void* __restrict__ idx) {
    int t = blockIdx.x * blockDim.x + threadIdx.x;
    if (t >= NTOK) return;
    int is64 = g_is64;
    int e0 = load_idx(idx, 2 * t, is64) & 7;
    int e1 = load_idx(idx, 2 * t + 1, is64) & 7;
    int p0 = atomicAdd(&g_cnt[e0], 1);
    g_list[e0][p0] = 2 * t;
    if (e1 != e0) { int p1 = atomicAdd(&g_cnt[e1], 1); g_list[e1][p1] = 2 * t + 1; }
}

// ---------------------------------------------------------------------------
// Elementwise fp32 -> bf16 hi/lo split (x and both W use this; no transpose)
// ---------------------------------------------------------------------------
__device__ __forceinline__ void split2(float a, float b, uint32_t& hp, uint32_t& lp) {
    __nv_bfloat162 h; h.x = __float2bfloat16(a); h.y = __float2bfloat16(b);
    __nv_bfloat162 l;
    l.x = __float2bfloat16(a - __bfloat162float(h.x));
    l.y = __float2bfloat16(b - __bfloat162float(h.y));
    hp = *(uint32_t*)&h; lp = *(uint32_t*)&l;
}

__global__ void convert_split_kernel(const float* __restrict__ src,
                                     size_t hi_off, size_t lo_off) {
    int g = blockIdx.x * blockDim.x + threadIdx.x;   // one float4 per thread
    float4 v = ((const float4*)src)[g];
    uint2 h, l;
    split2(v.x, v.y, h.x, l.x);
    split2(v.z, v.w, h.y, l.y);
    ((uint2*)(g_arena + hi_off))[g] = h;
    ((uint2*)(g_arena + lo_off))[g] = l;
}

// ---------------------------------------------------------------------------
// Grouped GEMM via mma.sync (HMMA), 3-term bf16 split.
// CTA tile 128x128, BK=32, 8 warps (2M x 4N), warp tile 64x32.
// A smem: [m][k], 80B pitch (conflict-free LDSM.x4).
// B smem: [k][n], 272B pitch (conflict-free LDSM.x2.trans).
// phase1: A=x-split gathered by slot>>1 -> h1-split, +b1, relu
// phase2: A=h1-split gathered by slot  -> even slot: w0eff*(acc+b2) -> out[t]
//                                        odd slot:  w1  *(acc+b2) -> scr2[t]
// ---------------------------------------------------------------------------
#define BK        32
#define A_PITCH   80
#define B_PITCH   272
#define A_TILE_SB (128 * A_PITCH)              // 10240
#define B_TILE_SB (32 * B_PITCH)               // 8704
#define OFF_AHI   0
#define OFF_ALO   (A_TILE_SB)
#define OFF_BHI   (2 * A_TILE_SB)
#define OFF_BLO   (2 * A_TILE_SB + B_TILE_SB)
#define STAGE_SB  (2 * A_TILE_SB + 2 * B_TILE_SB)   // 37888
#define OFF_MISC  (2 * STAGE_SB)                    // 75776
#define OFF_SLOT  (OFF_MISC + 0)
#define OFF_BIAS  (OFF_MISC + 512)
#define SMEM_TOTAL (OFF_MISC + 1024)                // 76800

__global__ void __launch_bounds__(256, 1)
moe_mma_kernel(const float* __restrict__ Bias,
               const void*  __restrict__ idx,
               const float* __restrict__ wts,
               float*       __restrict__ out,
               int phase)
{
    extern __shared__ char smem[];
    const int e   = blockIdx.z;
    const int cnt = g_cnt[e];
    const int m0  = blockIdx.y * 128;
    if (m0 >= cnt) return;
    const int n0  = blockIdx.x * 128;
    const int tid = threadIdx.x;
    const int l   = tid & 31;
    const int wid = tid >> 5;
    const int wm  = (wid & 1) * 64;
    const int wn  = (wid >> 1) * 32;

    const uint32_t sb = smem_u32(smem);
    int*   s_slot = (int*)(smem + OFF_SLOT);
    float* s_bias = (float*)(smem + OFF_BIAS);

    if (tid < 128) {
        int mi = m0 + tid;
        s_slot[tid] = (mi < cnt) ? g_list[e][mi] : -1;
        s_bias[tid] = Bias[(size_t)e * HDIM + n0 + tid];
    }
    __syncthreads();

    const unsigned char* Ah = g_arena + ((phase == 1) ? A_XHI : A_H1HI);
    const unsigned char* Al = g_arena + ((phase == 1) ? A_XLO : A_H1LO);
    const unsigned char* Bh = g_arena + ((phase == 1) ? A_W1HI : A_W2HI) + ((size_t)e << 21);
    const unsigned char* Bl = g_arena + ((phase == 1) ? A_W1LO : A_W2LO) + ((size_t)e << 21);

    // cp.async plan. A: unit u=tid+256i -> row=u>>2 (0..127), c=u&3 (16B of 64B row-chunk).
    //                B: unit u=tid+256i -> krow=u>>4 (0..31), nc=u&15 (16B of 256B row).
    uint32_t aso[2], ago[2], avn[2], bso[2], bgo[2];
    #pragma unroll
    for (int i = 0; i < 2; i++) {
        int u = tid + 256 * i;
        int arow = u >> 2, ac = u & 3;
        aso[i] = (uint32_t)(arow * A_PITCH + ac * 16);
        int slot = s_slot[arow];
        avn[i] = (slot >= 0) ? 16u : 0u;
        int ar = (slot >= 0) ? ((phase == 1) ? (slot >> 1) : slot) : 0;
        ago[i] = (uint32_t)ar * (HDIM * 2) + ac * 16;
        int krow = u >> 4, nc = u & 15;
        bso[i] = (uint32_t)(krow * B_PITCH + nc * 16);
        bgo[i] = (uint32_t)krow * (HDIM * 2) + (uint32_t)n0 * 2 + nc * 16;
    }

    float acc[4][4][4];
    #pragma unroll
    for (int a = 0; a < 4; a++)
        #pragma unroll
        for (int b = 0; b < 4; b++)
            #pragma unroll
            for (int r = 0; r < 4; r++) acc[a][b][r] = 0.f;

    // prologue: chunk 0 -> stage 0
    {
        const uint32_t d = sb;
        #pragma unroll
        for (int i = 0; i < 2; i++) {
            cp16(d + OFF_AHI + aso[i], Ah + ago[i], avn[i]);
            cp16(d + OFF_ALO + aso[i], Al + ago[i], avn[i]);
            cp16(d + OFF_BHI + bso[i], Bh + bgo[i], 16u);
            cp16(d + OFF_BLO + bso[i], Bl + bgo[i], 16u);
        }
        CP_COMMIT();
    }

    for (int c = 0; c < HDIM / BK; c++) {
        if (c + 1 < HDIM / BK) {
            const uint32_t ka = (uint32_t)(c + 1) * (BK * 2);       // A: +64 B/chunk
            const uint32_t kb = (uint32_t)(c + 1) * (BK * HDIM * 2); // B: +64 KiB/chunk
            const uint32_t d = sb + ((c + 1) & 1) * STAGE_SB;
            #pragma unroll
            for (int i = 0; i < 2; i++) {
                cp16(d + OFF_AHI + aso[i], Ah + ago[i] + ka, avn[i]);
                cp16(d + OFF_ALO + aso[i], Al + ago[i] + ka, avn[i]);
                cp16(d + OFF_BHI + bso[i], Bh + bgo[i] + kb, 16u);
                cp16(d + OFF_BLO + bso[i], Bl + bgo[i] + kb, 16u);
            }
            CP_COMMIT();
            CP_WAIT(1);
        } else {
            CP_WAIT(0);
        }
        __syncthreads();

        const uint32_t st = sb + (c & 1) * STAGE_SB;
        #pragma unroll
        for (int ks = 0; ks < 2; ks++) {
            const uint32_t kcolA = (uint32_t)((ks * 16 + (l >> 4) * 8) * 2);
            const uint32_t bkrow = (uint32_t)((ks * 16 + (l & 15)) * B_PITCH);
            uint32_t bh[4][2], bl[4][2];
            #pragma unroll
            for (int ni = 0; ni < 4; ni++) {
                uint32_t aB = st + bkrow + (uint32_t)((wn + ni * 8) * 2);
                LDM_X2T(bh[ni], aB + OFF_BHI);
                LDM_X2T(bl[ni], aB + OFF_BLO);
            }
            #pragma unroll
            for (int mi = 0; mi < 4; mi++) {
                uint32_t rA = (uint32_t)((wm + mi * 16 + (l & 15)) * A_PITCH) + kcolA;
                uint32_t ah[4], al[4];
                LDM_X4(ah, st + OFF_AHI + rA);
                LDM_X4(al, st + OFF_ALO + rA);
                #pragma unroll
                for (int ni = 0; ni < 4; ni++) {
                    MMA_BF16(acc[mi][ni], ah, bh[ni]);
                    MMA_BF16(acc[mi][ni], ah, bl[ni]);
                    MMA_BF16(acc[mi][ni], al, bh[ni]);
                }
            }
        }
        __syncthreads();
    }

    // ---- epilogue ----
    const int qr = l >> 2, qc = (l & 3) * 2;
    const int is64 = g_is64;
    __nv_bfloat16* h1h = (__nv_bfloat16*)(g_arena + A_H1HI);
    __nv_bfloat16* h1l = (__nv_bfloat16*)(g_arena + A_H1LO);
    float*         scr = (float*)(g_arena + A_SCR2);

    #pragma unroll
    for (int mi = 0; mi < 4; mi++) {
        #pragma unroll
        for (int h = 0; h < 2; h++) {
            int rl = wm + mi * 16 + qr + h * 8;
            int slot = s_slot[rl];
            if (slot < 0) continue;
            if (phase == 1) {
                __nv_bfloat16* oh = h1h + (size_t)slot * HDIM + n0;
                __nv_bfloat16* ol = h1l + (size_t)slot * HDIM + n0;
                #pragma unroll
                for (int ni = 0; ni < 4; ni++) {
                    int col = wn + ni * 8 + qc;
                    float v0 = fmaxf(acc[mi][ni][h * 2]     + s_bias[col],     0.f);
                    float v1 = fmaxf(acc[mi][ni][h * 2 + 1] + s_bias[col + 1], 0.f);
                    uint32_t hp, lp;
                    split2(v0, v1, hp, lp);
                    *(uint32_t*)(oh + col) = hp;
                    *(uint32_t*)(ol + col) = lp;
                }
            } else {
                int t = slot >> 1;
                float w;
                float* dst;
                if ((slot & 1) == 0) {
                    int e0 = load_idx(idx, 2 * t, is64) & 7;
                    int e1 = load_idx(idx, 2 * t + 1, is64) & 7;
                    w = wts[2 * t] + ((e1 == e0) ? wts[2 * t + 1] : 0.f);
                    dst = out + (size_t)t * HDIM + n0;
                } else {
                    w = wts[2 * t + 1];
                    dst = scr + (size_t)t * HDIM + n0;
                }
                #pragma unroll
                for (int ni = 0; ni < 4; ni++) {
                    int col = wn + ni * 8 + qc;
                    float2 v;
                    v.x = w * (acc[mi][ni][h * 2]     + s_bias[col]);
                    v.y = w * (acc[mi][ni][h * 2 + 1] + s_bias[col + 1]);
                    *(float2*)(dst + col) = v;
                }
            }
        }
    }
}

// ---------------------------------------------------------------------------
// Final add: out[t] += scr2[t] when the token has a distinct second expert.
// ---------------------------------------------------------------------------
__global__ void add_kernel(const void* __restrict__ idx, float* __restrict__ out) {
    int g = blockIdx.x * blockDim.x + threadIdx.x;
    if (g >= NTOK * (HDIM / 4)) return;
    int t = g / (HDIM / 4);
    int is64 = g_is64;
    int e0 = load_idx(idx, 2 * t, is64) & 7;
    int e1 = load_idx(idx, 2 * t + 1, is64) & 7;
    if (e1 == e0) return;
    const float* scr = (const float*)(g_arena + A_SCR2);
    float4 a = ((const float4*)out)[g];
    float4 b = ((const float4*)scr)[g];
    a.x += b.x; a.y += b.y; a.z += b.z; a.w += b.w;
    ((float4*)out)[g] = a;
}

// ---------------------------------------------------------------------------
extern "C" void kernel_launch(void* const* d_in, const int* in_sizes, int n_in,
                              void* d_out, int out_size)
{
    const float* hidden = (const float*)d_in[0];
    const void*  idx    = d_in[1];
    const float* wts    = (const float*)d_in[2];
    const float* w1     = (const float*)d_in[3];
    const float* b1     = (const float*)d_in[4];
    const float* w2     = (const float*)d_in[5];
    const float* b2     = (const float*)d_in[6];
    float*       out    = (float*)d_out;

    cudaFuncSetAttribute(moe_mma_kernel,
                         cudaFuncAttributeMaxDynamicSharedMemorySize, SMEM_TOTAL);

    zero_cnt_kernel<<<1, 32>>>();
    detect_kernel<<<16, 256>>>((const int*)idx);
    set_flag_kernel<<<1, 32>>>();
    route_kernel<<<(NTOK + 255) / 256, 256>>>(idx);

    // x and w1 splits (8,388,608 elems each -> 2,097,152 float4s -> 8192 blocks)
    convert_split_kernel<<<8192, 256>>>(hidden, A_XHI, A_XLO);
    convert_split_kernel<<<8192, 256>>>(w1, A_W1HI, A_W1LO);

    dim3 grid(HDIM / 128, NTOK / 128, NEXP);
    moe_mma_kernel<<<grid, 256, SMEM_TOTAL>>>(b1, idx, wts, out, 1);

    // w2 split overwrites the (now dead) x-split region
    convert_split_kernel<<<8192, 256>>>(w2, A_W2HI, A_W2LO);

    moe_mma_kernel<<<grid, 256, SMEM_TOTAL>>>(b2, idx, wts, out, 2);

    add_kernel<<<(NTOK * (HDIM / 4) + 255) / 256, 256>>>(idx, out);
}